// round 2
// baseline (speedup 1.0000x reference)
#include <cuda_runtime.h>
#include <cstdint>

#define NPTS   60000
#define KOFF   27
#define CIN    2
#define COUT   64
#define CELLS  960000        // 2*12*200*200
#define EPS_LN 1e-5f

#define NPAIRS (KOFF * NPTS)            // 1,620,000
#define ACT_WORDS ((CELLS + 31) / 32)   // 30,000

// Activity bitmap (device scratch; allocations are forbidden).
__device__ unsigned int g_active[ACT_WORDS];

// --------------------------------------------------------------------------
// Kernel 1: zero the output accumulator + activity bitmap.
// d_out is poisoned 0xAA before timing, and every graph replay must start
// from zeros, so this runs first each launch.
// --------------------------------------------------------------------------
__global__ void zero_kernel(float4* __restrict__ out) {
    const int total4 = CELLS * COUT / 4;    // 15,360,000 float4 stores
    int i = blockIdx.x * blockDim.x + threadIdx.x;
    if (i < total4) out[i] = make_float4(0.f, 0.f, 0.f, 0.f);
    if (i < ACT_WORDS) g_active[i] = 0u;
}

// --------------------------------------------------------------------------
// Kernel 2: scatter-add contributions.
// 16 threads handle one (k, n) pair; each thread computes 4 consecutive
// output channels and issues a single red.global.add.v4.f32 (sm_90+).
// Weights (27*2*64 f32 = 13.8 KB) are staged in shared memory.
// --------------------------------------------------------------------------
__global__ void scatter_kernel(const float* __restrict__ feat,     // [NPTS, 2]
                               const float* __restrict__ weight,   // [27, 2, 64]
                               const int*   __restrict__ scat,     // [27, NPTS]
                               float* __restrict__ out) {          // [CELLS, 64]
    __shared__ float sw[KOFF * CIN * COUT];   // 3456 floats
    for (int i = threadIdx.x; i < KOFF * CIN * COUT; i += blockDim.x)
        sw[i] = weight[i];
    __syncthreads();

    int gid    = blockIdx.x * blockDim.x + threadIdx.x;
    int pair   = gid >> 4;           // (k*NPTS + n)
    int lane16 = gid & 15;
    if (pair >= NPAIRS) return;

    int idx = scat[pair];
    if ((unsigned)idx >= (unsigned)CELLS) return;   // CELLS sentinel = OOB dump

    int k = pair / NPTS;
    int n = pair - k * NPTS;

    float f0 = feat[2 * n + 0];
    float f1 = feat[2 * n + 1];

    int q0 = lane16 * 4;
    const float* w0 = &sw[(k * 2 + 0) * COUT + q0];
    const float* w1 = &sw[(k * 2 + 1) * COUT + q0];

    float c0 = fmaf(f0, w0[0], f1 * w1[0]);
    float c1 = fmaf(f0, w0[1], f1 * w1[1]);
    float c2 = fmaf(f0, w0[2], f1 * w1[2]);
    float c3 = fmaf(f0, w0[3], f1 * w1[3]);

    float* p = out + (size_t)idx * COUT + q0;
    asm volatile("red.global.add.v4.f32 [%0], {%1, %2, %3, %4};"
                 :: "l"(p), "f"(c0), "f"(c1), "f"(c2), "f"(c3)
                 : "memory");

    if (lane16 == 0)
        atomicOr(&g_active[idx >> 5], 1u << (idx & 31));
}

// --------------------------------------------------------------------------
// Kernel 3: in-place LayerNorm + ReLU, one warp per cell.
// Lane i owns channels {2i, 2i+1}. Inactive cells are already zero (kernel 1
// zeroed them, scatter never touched them) -> skip entirely.
// --------------------------------------------------------------------------
__global__ void ln_kernel(const float* __restrict__ gamma,
                          const float* __restrict__ beta,
                          float* __restrict__ out) {
    int cell = blockIdx.x * (blockDim.x >> 5) + (threadIdx.x >> 5);
    int lane = threadIdx.x & 31;
    if (cell >= CELLS) return;

    bool active = (g_active[cell >> 5] >> (cell & 31)) & 1u;
    if (!active) return;   // value already 0.0 in out

    float2* p = reinterpret_cast<float2*>(out + (size_t)cell * COUT) + lane;
    float2 v = *p;

    float s = v.x + v.y;
    #pragma unroll
    for (int o = 16; o > 0; o >>= 1) s += __shfl_xor_sync(0xffffffffu, s, o);
    float mean = s * (1.f / COUT);

    float dx = v.x - mean, dy = v.y - mean;
    float sq = dx * dx + dy * dy;
    #pragma unroll
    for (int o = 16; o > 0; o >>= 1) sq += __shfl_xor_sync(0xffffffffu, sq, o);

    float inv = rsqrtf(sq * (1.f / COUT) + EPS_LN);

    float g0 = gamma[2 * lane], g1 = gamma[2 * lane + 1];
    float b0 = beta[2 * lane],  b1 = beta[2 * lane + 1];

    float r0 = fmaxf(fmaf(dx * inv, g0, b0), 0.f);
    float r1 = fmaxf(fmaf(dy * inv, g1, b1), 0.f);
    *p = make_float2(r0, r1);
}

// --------------------------------------------------------------------------
extern "C" void kernel_launch(void* const* d_in, const int* in_sizes, int n_in,
                              void* d_out, int out_size) {
    const float* feat   = (const float*)d_in[0];   // [60000, 2]
    const float* weight = (const float*)d_in[1];   // [27, 2, 64]
    const float* gamma  = (const float*)d_in[2];   // [64]
    const float* beta   = (const float*)d_in[3];   // [64]
    const int*   scat   = (const int*)d_in[4];     // [27, 60000]
    float* out = (float*)d_out;                    // [960000, 64]

    // 1) zero accumulator + activity bitmap
    {
        int total4 = CELLS * COUT / 4;
        int threads = 256;
        int blocks = (total4 + threads - 1) / threads;   // 60000
        zero_kernel<<<blocks, threads>>>((float4*)out);
    }

    // 2) scatter-add
    {
        int threads = 256;
        long long total = (long long)NPAIRS * 16;
        int blocks = (int)((total + threads - 1) / threads);  // 101,250
        scatter_kernel<<<blocks, threads>>>(feat, weight, scat, out);
    }

    // 3) layernorm + relu
    {
        int threads = 256;                   // 8 warps = 8 cells / block
        int blocks = (CELLS + 7) / 8;        // 120,000
        ln_kernel<<<blocks, threads>>>(gamma, beta, out);
    }
}

// round 3
// speedup vs baseline: 2.2207x; 2.2207x over previous
#include <cuda_runtime.h>
#include <cstdint>

#define NPTS   60000
#define KOFF   27
#define CIN    2
#define COUT   64
#define BD     2
#define DD     12
#define HH     200
#define WW     200
#define CELLS  960000        // 2*12*200*200
#define EPS_LN 1e-5f

// Dense cell -> point-id lookup grid (3.84 MB, L2-resident). -1 = empty.
__device__ int g_pointgrid[CELLS];

// --------------------------------------------------------------------------
// Kernel 1: init point grid to -1 (vectorized int4 stores).
// --------------------------------------------------------------------------
__global__ void init_grid_kernel() {
    int i = blockIdx.x * blockDim.x + threadIdx.x;
    if (i < CELLS / 4)
        reinterpret_cast<int4*>(g_pointgrid)[i] = make_int4(-1, -1, -1, -1);
}

// --------------------------------------------------------------------------
// Kernel 2: fill point grid. scat[13*NPTS + n] is point n's own cell index
// (center offset, always in bounds). Points are unique -> no races.
// --------------------------------------------------------------------------
__global__ void fill_grid_kernel(const int* __restrict__ scat) {
    int n = blockIdx.x * blockDim.x + threadIdx.x;
    if (n < NPTS)
        g_pointgrid[scat[13 * NPTS + n]] = n;
}

// --------------------------------------------------------------------------
// Kernel 3: fused gather-conv + LayerNorm + ReLU.
// One warp per output cell (4 cells per warp, serial). Lane i owns channels
// {2i, 2i+1}. Lanes 0..26 probe the 27-neighborhood in the point grid;
// hits are broadcast via ballot/shfl; weights staged in smem as float2.
// Each cell is written exactly once -> no pre-zero of d_out needed.
// --------------------------------------------------------------------------
#define CELLS_PER_WARP 4
#define WARPS_PER_BLOCK 8

__global__ __launch_bounds__(256) void fused_kernel(
        const float2* __restrict__ feat,     // [NPTS] as float2
        const float2* __restrict__ weight2,  // [27*2*32] float2 view of [27,2,64]
        const float*  __restrict__ gamma,    // [64]
        const float*  __restrict__ beta,     // [64]
        float* __restrict__ out) {           // [CELLS, 64]
    __shared__ float2 sw[KOFF * CIN * (COUT / 2)];   // 1728 float2 = 13824 B
    for (int i = threadIdx.x; i < KOFF * CIN * (COUT / 2); i += blockDim.x)
        sw[i] = weight2[i];
    __syncthreads();

    const int lane = threadIdx.x & 31;
    const int warp = blockIdx.x * WARPS_PER_BLOCK + (threadIdx.x >> 5);

    const float g0 = gamma[2 * lane], g1 = gamma[2 * lane + 1];
    const float b0 = beta[2 * lane],  b1 = beta[2 * lane + 1];

    // precompute this lane's neighbor offset (lanes 0..26)
    const int dz = lane / 9 - 1;
    const int dy = (lane / 3) % 3 - 1;
    const int dx = lane % 3 - 1;
    const int doff = (dz * HH + dy) * WW + dx;

    const int cell0 = warp * CELLS_PER_WARP;

    #pragma unroll
    for (int ci = 0; ci < CELLS_PER_WARP; ci++) {
        const int cell = cell0 + ci;
        if (cell >= CELLS) return;

        // decode (b implicit; neighbors stay in same b by construction)
        int x = cell % WW;
        int t = cell / WW;
        int y = t % HH;
        int z = (t / HH) % DD;

        int point = -1;
        if (lane < KOFF) {
            int nz = z + dz, ny = y + dy, nx = x + dx;
            if ((unsigned)nz < DD && (unsigned)ny < HH && (unsigned)nx < WW)
                point = __ldg(&g_pointgrid[cell + doff]);
        }

        const unsigned act = __ballot_sync(0xffffffffu, point >= 0);
        float2* po = reinterpret_cast<float2*>(out + (size_t)cell * COUT) + lane;

        if (act == 0u) {                 // inactive cell: just clear poison
            *po = make_float2(0.f, 0.f);
            continue;
        }

        float fx = 0.f, fy = 0.f;
        if (point >= 0) {
            float2 f = __ldg(&feat[point]);
            fx = f.x; fy = f.y;
        }

        float a0 = 0.f, a1 = 0.f;
        unsigned hits = act;
        while (hits) {
            int j = __ffs(hits) - 1;
            hits &= hits - 1;
            float f0 = __shfl_sync(0xffffffffu, fx, j);
            float f1 = __shfl_sync(0xffffffffu, fy, j);
            float2 w0 = sw[(j * 2 + 0) * (COUT / 2) + lane];
            float2 w1 = sw[(j * 2 + 1) * (COUT / 2) + lane];
            a0 = fmaf(f0, w0.x, fmaf(f1, w1.x, a0));
            a1 = fmaf(f0, w0.y, fmaf(f1, w1.y, a1));
        }

        // LayerNorm over 64 channels (2 per lane) + ReLU
        float s = a0 + a1;
        #pragma unroll
        for (int o = 16; o > 0; o >>= 1) s += __shfl_xor_sync(0xffffffffu, s, o);
        const float mean = s * (1.f / COUT);

        const float d0 = a0 - mean, d1 = a1 - mean;
        float sq = d0 * d0 + d1 * d1;
        #pragma unroll
        for (int o = 16; o > 0; o >>= 1) sq += __shfl_xor_sync(0xffffffffu, sq, o);

        const float inv = rsqrtf(sq * (1.f / COUT) + EPS_LN);

        float r0 = fmaxf(fmaf(d0 * inv, g0, b0), 0.f);
        float r1 = fmaxf(fmaf(d1 * inv, g1, b1), 0.f);
        *po = make_float2(r0, r1);
    }
}

// --------------------------------------------------------------------------
extern "C" void kernel_launch(void* const* d_in, const int* in_sizes, int n_in,
                              void* d_out, int out_size) {
    const float* feat   = (const float*)d_in[0];   // [60000, 2]
    const float* weight = (const float*)d_in[1];   // [27, 2, 64]
    const float* gamma  = (const float*)d_in[2];   // [64]
    const float* beta   = (const float*)d_in[3];   // [64]
    const int*   scat   = (const int*)d_in[4];     // [27, 60000]
    float* out = (float*)d_out;                    // [960000, 64]

    // 1) init point grid
    init_grid_kernel<<<(CELLS / 4 + 255) / 256, 256>>>();

    // 2) fill point grid from the center-offset scatter row
    fill_grid_kernel<<<(NPTS + 255) / 256, 256>>>(scat);

    // 3) fused gather + LN + ReLU (writes every output cell exactly once)
    {
        int cells_per_block = 32 * WARPS_PER_BLOCK * CELLS_PER_WARP / 32; // 32
        int blocks = (CELLS + cells_per_block - 1) / cells_per_block;     // 30000
        fused_kernel<<<blocks, 256>>>((const float2*)feat,
                                      (const float2*)weight,
                                      gamma, beta, out);
    }
}

// round 4
// speedup vs baseline: 2.2448x; 1.0108x over previous
#include <cuda_runtime.h>
#include <cstdint>

#define NPTS   60000
#define KOFF   27
#define CIN    2
#define COUT   64
#define DD     12
#define HH     200
#define WW     200
#define CELLS  960000        // 2*12*200*200, divisible by 32
#define EPS_LN 1e-5f

#define CELLS_PER_WARP  4
#define WARPS_PER_BLOCK 8
#define CELLS_PER_BLOCK (CELLS_PER_WARP * WARPS_PER_BLOCK)   // 32

// Dense cell -> point-id lookup grid (3.84 MB, L2-resident). -1 = empty.
__device__ int g_pointgrid[CELLS];

// --------------------------------------------------------------------------
// Kernel 1: init point grid to -1.
// --------------------------------------------------------------------------
__global__ void init_grid_kernel() {
    int i = blockIdx.x * blockDim.x + threadIdx.x;
    if (i < CELLS / 4)
        reinterpret_cast<int4*>(g_pointgrid)[i] = make_int4(-1, -1, -1, -1);
}

// --------------------------------------------------------------------------
// Kernel 2: fill point grid. scat[13*NPTS + n] is point n's own cell index.
// --------------------------------------------------------------------------
__global__ void fill_grid_kernel(const int* __restrict__ scat) {
    int n = blockIdx.x * blockDim.x + threadIdx.x;
    if (n < NPTS)
        g_pointgrid[scat[13 * NPTS + n]] = n;
}

// --------------------------------------------------------------------------
// Kernel 3: fused gather-conv + LayerNorm + ReLU, phase-batched for ILP.
// One warp handles 4 cells. Lane i owns channels {2i, 2i+1}.
// --------------------------------------------------------------------------
__global__ __launch_bounds__(256) void fused_kernel(
        const float2* __restrict__ feat,     // [NPTS] as float2
        const float2* __restrict__ weight2,  // float2 view of [27,2,64]
        const float*  __restrict__ gamma,
        const float*  __restrict__ beta,
        float* __restrict__ out) {           // [CELLS, 64]
    __shared__ float2 sw[KOFF * CIN * (COUT / 2)];                      // 13824 B
    __shared__ float2 sfeat[WARPS_PER_BLOCK][CELLS_PER_WARP][32];      //  8192 B

    for (int i = threadIdx.x; i < KOFF * CIN * (COUT / 2); i += blockDim.x)
        sw[i] = weight2[i];
    __syncthreads();

    const int lane = threadIdx.x & 31;
    const int wib  = threadIdx.x >> 5;
    const int cell0 = (blockIdx.x * WARPS_PER_BLOCK + wib) * CELLS_PER_WARP;

    const float gg0 = gamma[2 * lane], gg1 = gamma[2 * lane + 1];
    const float bb0 = beta[2 * lane],  bb1 = beta[2 * lane + 1];

    // this lane's neighborhood offset (lanes 0..26)
    const int dz = lane / 9 - 1;
    const int dy = (lane / 3) % 3 - 1;
    const int dx = lane % 3 - 1;
    const int doff = (dz * HH + dy) * WW + dx;
    const bool probing = (lane < KOFF);

    // ---- phase 1: all grid probes in flight (MLP=4 hides L2 latency) ----
    int pt[CELLS_PER_WARP];
    #pragma unroll
    for (int ci = 0; ci < CELLS_PER_WARP; ci++) {
        const int cell = cell0 + ci;
        const int x = cell % WW;
        const int t = cell / WW;
        const int y = t % HH;
        const int z = (t / HH) % DD;
        bool ok = probing &&
                  (unsigned)(z + dz) < DD &&
                  (unsigned)(y + dy) < HH &&
                  (unsigned)(x + dx) < WW;
        pt[ci] = ok ? __ldg(&g_pointgrid[cell + doff]) : -1;
    }

    // ---- phase 2: ballots + feature loads -> smem bounce ----
    unsigned act[CELLS_PER_WARP];
    #pragma unroll
    for (int ci = 0; ci < CELLS_PER_WARP; ci++)
        act[ci] = __ballot_sync(0xffffffffu, pt[ci] >= 0);

    #pragma unroll
    for (int ci = 0; ci < CELLS_PER_WARP; ci++)
        if (pt[ci] >= 0)
            sfeat[wib][ci][lane] = __ldg(&feat[pt[ci]]);
    __syncwarp();

    // ---- phase 3: accumulate (independent LDS broadcasts, no shfl chain) ----
    float A0[CELLS_PER_WARP], A1[CELLS_PER_WARP], S[CELLS_PER_WARP];
    #pragma unroll
    for (int ci = 0; ci < CELLS_PER_WARP; ci++) {
        float a0 = 0.f, a1 = 0.f;
        unsigned hits = act[ci];
        while (hits) {
            const int j = __ffs(hits) - 1;
            hits &= hits - 1;
            const float2 fj = sfeat[wib][ci][j];
            const float2 w0 = sw[(j * 2 + 0) * (COUT / 2) + lane];
            const float2 w1 = sw[(j * 2 + 1) * (COUT / 2) + lane];
            a0 = fmaf(fj.x, w0.x, fmaf(fj.y, w1.x, a0));
            a1 = fmaf(fj.x, w0.y, fmaf(fj.y, w1.y, a1));
        }
        A0[ci] = a0; A1[ci] = a1; S[ci] = a0 + a1;
    }

    // ---- phase 4: interleaved butterfly reductions (4 independent chains) --
    #pragma unroll
    for (int o = 16; o > 0; o >>= 1) {
        #pragma unroll
        for (int ci = 0; ci < CELLS_PER_WARP; ci++)
            S[ci] += __shfl_xor_sync(0xffffffffu, S[ci], o);
    }

    float D0[CELLS_PER_WARP], D1[CELLS_PER_WARP], SQ[CELLS_PER_WARP];
    #pragma unroll
    for (int ci = 0; ci < CELLS_PER_WARP; ci++) {
        const float mean = S[ci] * (1.f / COUT);
        D0[ci] = A0[ci] - mean;
        D1[ci] = A1[ci] - mean;
        SQ[ci] = D0[ci] * D0[ci] + D1[ci] * D1[ci];
    }
    #pragma unroll
    for (int o = 16; o > 0; o >>= 1) {
        #pragma unroll
        for (int ci = 0; ci < CELLS_PER_WARP; ci++)
            SQ[ci] += __shfl_xor_sync(0xffffffffu, SQ[ci], o);
    }

    // ---- phase 5: normalize + relu + store (exact zeros when inactive) ----
    #pragma unroll
    for (int ci = 0; ci < CELLS_PER_WARP; ci++) {
        const float inv = rsqrtf(SQ[ci] * (1.f / COUT) + EPS_LN);
        float r0 = fmaxf(fmaf(D0[ci] * inv, gg0, bb0), 0.f);
        float r1 = fmaxf(fmaf(D1[ci] * inv, gg1, bb1), 0.f);
        if (act[ci] == 0u) { r0 = 0.f; r1 = 0.f; }
        float2* po = reinterpret_cast<float2*>(out + (size_t)(cell0 + ci) * COUT) + lane;
        *po = make_float2(r0, r1);
    }
}

// --------------------------------------------------------------------------
extern "C" void kernel_launch(void* const* d_in, const int* in_sizes, int n_in,
                              void* d_out, int out_size) {
    const float* feat   = (const float*)d_in[0];   // [60000, 2]
    const float* weight = (const float*)d_in[1];   // [27, 2, 64]
    const float* gamma  = (const float*)d_in[2];   // [64]
    const float* beta   = (const float*)d_in[3];   // [64]
    const int*   scat   = (const int*)d_in[4];     // [27, 60000]
    float* out = (float*)d_out;                    // [960000, 64]

    init_grid_kernel<<<(CELLS / 4 + 255) / 256, 256>>>();
    fill_grid_kernel<<<(NPTS + 255) / 256, 256>>>(scat);
    fused_kernel<<<CELLS / CELLS_PER_BLOCK, 256>>>(
        (const float2*)feat, (const float2*)weight, gamma, beta, out);
}

// round 5
// speedup vs baseline: 2.8927x; 1.2887x over previous
#include <cuda_runtime.h>
#include <cstdint>

#define NPTS   60000
#define KOFF   27
#define CIN    2
#define COUT   64
#define BB     2
#define DD     12
#define HH     200
#define WW     200
#define CELLS  960000        // 2*12*200*200
#define EPS_LN 1e-5f

#define ROWS_TOTAL (BB * DD * HH)        // 4800 blocks
#define WARPS_PER_BLOCK 8
#define CELLS_PER_WARP  (WW / WARPS_PER_BLOCK)   // 25
#define CHUNK 5                                   // cells processed per phase

#define GROW 202                                  // padded row: [-1 | 200 | -1]

// Dense cell -> point-id lookup grid (3.84 MB, L2-resident). -1 = empty.
__device__ int g_pointgrid[CELLS];

// --------------------------------------------------------------------------
// Kernel 1: init point grid to -1.
// --------------------------------------------------------------------------
__global__ void init_grid_kernel() {
    int i = blockIdx.x * blockDim.x + threadIdx.x;
    if (i < CELLS / 4)
        reinterpret_cast<int4*>(g_pointgrid)[i] = make_int4(-1, -1, -1, -1);
}

// --------------------------------------------------------------------------
// Kernel 2: fill point grid. scat[13*NPTS + n] is point n's own cell index.
// --------------------------------------------------------------------------
__global__ void fill_grid_kernel(const int* __restrict__ scat) {
    int n = blockIdx.x * blockDim.x + threadIdx.x;
    if (n < NPTS)
        g_pointgrid[scat[13 * NPTS + n]] = n;
}

// --------------------------------------------------------------------------
// Kernel 3: fused gather-conv + LayerNorm + ReLU.
// One block per (b, z, y) row of 200 cells. The 9 neighbor grid rows are
// staged into smem with halo; probes are LDS. Warp handles 25 cells in
// chunks of 5 (phase-batched). Lane i owns channels {2i, 2i+1}.
// --------------------------------------------------------------------------
__global__ __launch_bounds__(256) void fused_kernel(
        const float2* __restrict__ feat,     // [NPTS] as float2
        const float2* __restrict__ weight2,  // float2 view of [27,2,64]
        const float*  __restrict__ gamma,
        const float*  __restrict__ beta,
        float* __restrict__ out) {           // [CELLS, 64]
    __shared__ float2 sw[KOFF * CIN * (COUT / 2)];            // 13824 B
    __shared__ int    sgrid[9 * GROW];                        //  7272 B
    __shared__ float2 sfeat[WARPS_PER_BLOCK][CHUNK][32];      // 10240 B

    // decode row
    const int row = blockIdx.x;          // (b*DD + z)*HH + y
    const int y   = row % HH;
    const int bz  = row / HH;            // b*DD + z
    const int z   = bz % DD;
    const int rowbase = row * WW;        // linear cell index of x=0

    // ---- stage weights ----
    for (int i = threadIdx.x; i < KOFF * CIN * (COUT / 2); i += blockDim.x)
        sw[i] = weight2[i];

    // ---- stage 9 neighbor grid rows with halo ----
    for (int i = threadIdx.x; i < 9 * GROW; i += blockDim.x) {
        const int r  = i / GROW;         // 0..8 -> (dz+1)*3 + (dy+1)
        const int c  = i - r * GROW;     // 0..201 -> x = c-1
        const int dz = r / 3 - 1;
        const int dy = r % 3 - 1;
        const int nz = z + dz, ny = y + dy, nx = c - 1;
        int v = -1;
        if ((unsigned)nz < DD && (unsigned)ny < HH && (unsigned)nx < WW)
            v = g_pointgrid[rowbase + (dz * HH + dy) * WW + nx];
        sgrid[i] = v;
    }
    __syncthreads();

    const int lane = threadIdx.x & 31;
    const int wib  = threadIdx.x >> 5;

    const float gg0 = gamma[2 * lane], gg1 = gamma[2 * lane + 1];
    const float bb0 = beta[2 * lane],  bb1 = beta[2 * lane + 1];

    // lane -> (k, smem probe base)
    const int dxl   = lane % 3;                    // dx+1 for lanes<27
    const int srow  = (lane < KOFF) ? (lane / 3) : 0;   // (dz+1)*3+(dy+1)
    const int pbase = srow * GROW + dxl;           // + x gives probe index
    const bool probing = (lane < KOFF);

    const int x0 = wib * CELLS_PER_WARP;

    for (int c0 = 0; c0 < CELLS_PER_WARP; c0 += CHUNK) {
        // ---- phase 1: probes (LDS) ----
        int pt[CHUNK];
        #pragma unroll
        for (int ci = 0; ci < CHUNK; ci++) {
            const int x = x0 + c0 + ci;
            pt[ci] = probing ? sgrid[pbase + x] : -1;
        }

        // ---- phase 2: ballots + feature gather -> smem bounce ----
        unsigned act[CHUNK];
        #pragma unroll
        for (int ci = 0; ci < CHUNK; ci++)
            act[ci] = __ballot_sync(0xffffffffu, pt[ci] >= 0);
        #pragma unroll
        for (int ci = 0; ci < CHUNK; ci++)
            if (pt[ci] >= 0)
                sfeat[wib][ci][lane] = __ldg(&feat[pt[ci]]);
        __syncwarp();

        // ---- phase 3: accumulate ----
        float A0[CHUNK], A1[CHUNK], S[CHUNK];
        #pragma unroll
        for (int ci = 0; ci < CHUNK; ci++) {
            float a0 = 0.f, a1 = 0.f;
            unsigned hits = act[ci];
            while (hits) {
                const int j = __ffs(hits) - 1;
                hits &= hits - 1;
                const float2 fj = sfeat[wib][ci][j];
                const float2 w0 = sw[(j * 2 + 0) * (COUT / 2) + lane];
                const float2 w1 = sw[(j * 2 + 1) * (COUT / 2) + lane];
                a0 = fmaf(fj.x, w0.x, fmaf(fj.y, w1.x, a0));
                a1 = fmaf(fj.x, w0.y, fmaf(fj.y, w1.y, a1));
            }
            A0[ci] = a0; A1[ci] = a1; S[ci] = a0 + a1;
        }

        // ---- phase 4: interleaved butterflies ----
        #pragma unroll
        for (int o = 16; o > 0; o >>= 1) {
            #pragma unroll
            for (int ci = 0; ci < CHUNK; ci++)
                S[ci] += __shfl_xor_sync(0xffffffffu, S[ci], o);
        }
        float D0[CHUNK], D1[CHUNK], SQ[CHUNK];
        #pragma unroll
        for (int ci = 0; ci < CHUNK; ci++) {
            const float mean = S[ci] * (1.f / COUT);
            D0[ci] = A0[ci] - mean;
            D1[ci] = A1[ci] - mean;
            SQ[ci] = D0[ci] * D0[ci] + D1[ci] * D1[ci];
        }
        #pragma unroll
        for (int o = 16; o > 0; o >>= 1) {
            #pragma unroll
            for (int ci = 0; ci < CHUNK; ci++)
                SQ[ci] += __shfl_xor_sync(0xffffffffu, SQ[ci], o);
        }

        // ---- phase 5: normalize + relu + streaming store ----
        #pragma unroll
        for (int ci = 0; ci < CHUNK; ci++) {
            const float inv = rsqrtf(SQ[ci] * (1.f / COUT) + EPS_LN);
            float r0 = fmaxf(fmaf(D0[ci] * inv, gg0, bb0), 0.f);
            float r1 = fmaxf(fmaf(D1[ci] * inv, gg1, bb1), 0.f);
            if (act[ci] == 0u) { r0 = 0.f; r1 = 0.f; }
            const int cell = rowbase + x0 + c0 + ci;
            float2* po = reinterpret_cast<float2*>(out + (size_t)cell * COUT) + lane;
            __stcs(po, make_float2(r0, r1));   // streaming: don't thrash L2
        }
    }
}

// --------------------------------------------------------------------------
extern "C" void kernel_launch(void* const* d_in, const int* in_sizes, int n_in,
                              void* d_out, int out_size) {
    const float* feat   = (const float*)d_in[0];   // [60000, 2]
    const float* weight = (const float*)d_in[1];   // [27, 2, 64]
    const float* gamma  = (const float*)d_in[2];   // [64]
    const float* beta   = (const float*)d_in[3];   // [64]
    const int*   scat   = (const int*)d_in[4];     // [27, 60000]
    float* out = (float*)d_out;                    // [960000, 64]

    init_grid_kernel<<<(CELLS / 4 + 255) / 256, 256>>>();
    fill_grid_kernel<<<(NPTS + 255) / 256, 256>>>(scat);
    fused_kernel<<<ROWS_TOTAL, 256>>>(
        (const float2*)feat, (const float2*)weight, gamma, beta, out);
}